// round 12
// baseline (speedup 1.0000x reference)
#include <cuda_runtime.h>
#include <mma.h>
#include <cstdint>

using namespace nvcuda;

#define B_ 4096
#define H_ 1024
#define V_ 32000

// -------- scratch (device globals: allocation-free per harness rules) --------
__device__ float g_zf[(size_t)B_ * H_];
__device__ float g_zi[(size_t)B_ * H_];
__device__ float g_zc[(size_t)B_ * H_];
__device__ float g_zo[(size_t)B_ * H_];
__device__ float g_ct[(size_t)B_ * H_];
__device__ float g_ht[(size_t)B_ * H_];
__device__ float g_htr[(size_t)B_ * H_];        // tf32-rounded Ht  (vocab A)
__device__ float g_ctr[(size_t)B_ * H_];        // tf32-rounded Ct  (peephole A)
__device__ float g_xr [(size_t)B_ * H_];        // tf32-rounded x
__device__ float g_hr [(size_t)B_ * H_];        // tf32-rounded h
__device__ float g_cr [(size_t)B_ * H_];        // tf32-rounded c
__device__ float g_w  [(size_t)11 * H_ * H_];   // 11 tf32-rounded [1024x1024] weights
__device__ float g_wop[(size_t)H_ * V_];        // tf32-rounded w_op

constexpr int BM = 128, BN = 128, BK = 32;
constexpr int APAD = 8, BPAD = 8;
constexpr int A_ROW = BK + APAD;          // 40 floats
constexpr int B_ROW = BN + BPAD;          // 136 floats

__device__ __forceinline__ float sigmoidf_(float x) {
    return 1.0f / (1.0f + expf(-x));
}

// -------- generic tf32 pre-round (same cvt.rna bits as the old in-loop path) --------
__global__ void round_buf(const float* __restrict__ src, float* __restrict__ dst, size_t n4)
{
    size_t i = (size_t)blockIdx.x * blockDim.x + threadIdx.x;
    if (i < n4) {
        float4 v = ((const float4*)src)[i];
        v.x = wmma::__float_to_tf32(v.x);
        v.y = wmma::__float_to_tf32(v.y);
        v.z = wmma::__float_to_tf32(v.z);
        v.w = wmma::__float_to_tf32(v.w);
        ((float4*)dst)[i] = v;
    }
}

// ============ unified simple GEMM: conversion-free, 2 CTAs/SM (R11-proven config) ============
// C[bm,bn] = epi( sum_p A_p @ W_p  [+C if MODE==1] ), A stride 1024, B/C stride N.
// MODE: 0 = store, 1 = accumulate, 2 = sigmoid(store).
template <int MODE, int NPAIR>
__global__ __launch_bounds__(256, 2) void sgemm(
    const float* __restrict__ A0, const float* __restrict__ W0,
    const float* __restrict__ A1, const float* __restrict__ W1,
    const float* __restrict__ A2, const float* __restrict__ W2,
    float* __restrict__ C, int N)
{
    __shared__ __align__(16) float As[BM][A_ROW];
    __shared__ __align__(16) float Bs[BK][B_ROW];

    const int tid    = threadIdx.x;
    const int wid    = tid >> 5;
    const int warp_m = wid & 3;
    const int warp_n = wid >> 2;
    const int bm     = blockIdx.y * BM;
    const int bn     = blockIdx.x * BN;

    wmma::fragment<wmma::accumulator, 16, 16, 8, float> acc[2][4];
    #pragma unroll
    for (int i = 0; i < 2; i++)
        #pragma unroll
        for (int j = 0; j < 4; j++) {
            if (MODE == 1) {
                const float* cp = C + (size_t)(bm + warp_m * 32 + i * 16) * N
                                    + (bn + warp_n * 64 + j * 16);
                wmma::load_matrix_sync(acc[i][j], cp, N, wmma::mem_row_major);
            } else {
                wmma::fill_fragment(acc[i][j], 0.0f);
            }
        }

    const float* Aps[3] = {A0, A1, A2};
    const float* Wps[3] = {W0, W1, W2};
    const int NS = NPAIR * 32;

    const int ar = tid >> 3;             // 0..31
    const int ac = (tid & 7) * 4;        // 0..28
    const int br = tid >> 5;             // 0..7
    const int bc = (tid & 31) * 4;       // 0..124

    #pragma unroll 1
    for (int s = 0; s < NS; s++) {
        const int p  = s >> 5;
        const int k0 = (s & 31) * BK;
        const float* __restrict__ A = Aps[p];
        const float* __restrict__ W = Wps[p];

        #pragma unroll
        for (int rr = 0; rr < 4; rr++) {
            float4 v = *(const float4*)(A + (size_t)(bm + ar + rr * 32) * 1024 + k0 + ac);
            *(float4*)&As[ar + rr * 32][ac] = v;
        }
        #pragma unroll
        for (int rr = 0; rr < 4; rr++) {
            float4 v = *(const float4*)(W + (size_t)(k0 + br + rr * 8) * N + bn + bc);
            *(float4*)&Bs[br + rr * 8][bc] = v;
        }
        __syncthreads();

        #pragma unroll
        for (int kk = 0; kk < BK; kk += 8) {
            wmma::fragment<wmma::matrix_a, 16, 16, 8, wmma::precision::tf32, wmma::row_major> af[2];
            wmma::fragment<wmma::matrix_b, 16, 16, 8, wmma::precision::tf32, wmma::row_major> bf[4];
            #pragma unroll
            for (int i = 0; i < 2; i++)
                wmma::load_matrix_sync(af[i], &As[warp_m * 32 + i * 16][kk], A_ROW);
            #pragma unroll
            for (int j = 0; j < 4; j++)
                wmma::load_matrix_sync(bf[j], &Bs[kk][warp_n * 64 + j * 16], B_ROW);
            #pragma unroll
            for (int i = 0; i < 2; i++)
                #pragma unroll
                for (int j = 0; j < 4; j++)
                    wmma::mma_sync(acc[i][j], af[i], bf[j], acc[i][j]);
        }
        __syncthreads();
    }

    #pragma unroll
    for (int i = 0; i < 2; i++)
        #pragma unroll
        for (int j = 0; j < 4; j++) {
            if (MODE == 2) {
                #pragma unroll
                for (int t = 0; t < acc[i][j].num_elements; t++)
                    acc[i][j].x[t] = sigmoidf_(acc[i][j].x[t]);
            }
            float* cp = C + (size_t)(bm + warp_m * 32 + i * 16) * N
                          + (bn + warp_n * 64 + j * 16);
            wmma::store_matrix_sync(cp, acc[i][j], N, wmma::mem_row_major);
        }
}

// ======================= elementwise =======================
// Ct (exact) -> ct; Ct (tf32-rounded) -> ctr for the peephole GEMM
__global__ void lstm_ew1(const float* __restrict__ zf, const float* __restrict__ zi,
                         const float* __restrict__ zc, const float* __restrict__ c,
                         float* __restrict__ ct, float* __restrict__ ctr, int n)
{
    int i = blockIdx.x * blockDim.x + threadIdx.x;
    if (i < n) {
        float v = sigmoidf_(zf[i]) * c[i] + sigmoidf_(zi[i]) * tanhf(zc[i]);
        ct[i]  = v;
        ctr[i] = wmma::__float_to_tf32(v);
    }
}
// Ht (exact) -> ht; Ht (tf32-rounded) -> htr for the vocab GEMM
__global__ void lstm_ew2(const float* __restrict__ zo, const float* __restrict__ ct,
                         float* __restrict__ ht, float* __restrict__ htr, int n)
{
    int i = blockIdx.x * blockDim.x + threadIdx.x;
    if (i < n) {
        float v = sigmoidf_(zo[i]) * tanhf(ct[i]);
        ht[i]  = v;
        htr[i] = wmma::__float_to_tf32(v);
    }
}

extern "C" void kernel_launch(void* const* d_in, const int* in_sizes, int n_in,
                              void* d_out, int out_size)
{
    const float* x          = (const float*)d_in[0];
    const float* h          = (const float*)d_in[1];
    const float* c          = (const float*)d_in[2];
    const float* w_forget   = (const float*)d_in[3];
    const float* w_input    = (const float*)d_in[4];
    const float* w_output   = (const float*)d_in[5];
    const float* w_c_dash   = (const float*)d_in[6];
    const float* w_forget_c = (const float*)d_in[7];
    const float* w_input_c  = (const float*)d_in[8];
    const float* w_output_c = (const float*)d_in[9];
    const float* w_op       = (const float*)d_in[10];
    const float* w_ip_f     = (const float*)d_in[11];
    const float* w_ip_i     = (const float*)d_in[12];
    const float* w_ip_o     = (const float*)d_in[13];
    const float* w_ip_c     = (const float*)d_in[14];
    float* out = (float*)d_out;

    float *zf, *zi, *zc, *zo, *ctbuf, *htbuf, *htr, *ctr, *xr, *hr, *cr, *wsc, *wop;
    cudaGetSymbolAddress((void**)&zf, g_zf);
    cudaGetSymbolAddress((void**)&zi, g_zi);
    cudaGetSymbolAddress((void**)&zc, g_zc);
    cudaGetSymbolAddress((void**)&zo, g_zo);
    cudaGetSymbolAddress((void**)&ctbuf, g_ct);
    cudaGetSymbolAddress((void**)&htbuf, g_ht);
    cudaGetSymbolAddress((void**)&htr, g_htr);
    cudaGetSymbolAddress((void**)&ctr, g_ctr);
    cudaGetSymbolAddress((void**)&xr, g_xr);
    cudaGetSymbolAddress((void**)&hr, g_hr);
    cudaGetSymbolAddress((void**)&cr, g_cr);
    cudaGetSymbolAddress((void**)&wsc, g_w);
    cudaGetSymbolAddress((void**)&wop, g_wop);

    const size_t BV = (size_t)B_ * V_;
    const size_t BH = (size_t)B_ * H_;
    const size_t HH = (size_t)H_ * H_;
    float* ht_out = ((size_t)out_size >= BV + 2 * BH) ? (out + BV)      : htbuf;
    float* ct_out = ((size_t)out_size >= BV + 2 * BH) ? (out + BV + BH) : ctbuf;

    dim3 blk(256);
    dim3 g_h(8, 32);        // gate/peephole grids
    dim3 g_v(250, 32);      // vocab grid

    // Rounded weight slots in g_w:
    float* r_wipf = wsc + 0  * HH;  float* r_wipi = wsc + 1  * HH;
    float* r_wipc = wsc + 2  * HH;  float* r_wipo = wsc + 3  * HH;
    float* r_wf   = wsc + 4  * HH;  float* r_wi   = wsc + 5  * HH;
    float* r_wc   = wsc + 6  * HH;  float* r_wo   = wsc + 7  * HH;
    float* r_pf   = wsc + 8  * HH;  float* r_pi   = wsc + 9  * HH;
    float* r_po   = wsc + 10 * HH;

    // ---- pre-round everything the GEMMs consume (identical cvt.rna bits) ----
    const size_t n4_bh = BH / 4;          // 1,048,576 -> 4096 blocks
    const size_t n4_hh = HH / 4;          // 262,144  -> 1024 blocks
    const size_t n4_wop = (size_t)H_ * V_ / 4;   // 8,192,000 -> 32000 blocks
    round_buf<<<(unsigned)((n4_bh + 255) / 256), blk>>>(x, xr, n4_bh);
    round_buf<<<(unsigned)((n4_bh + 255) / 256), blk>>>(h, hr, n4_bh);
    round_buf<<<(unsigned)((n4_bh + 255) / 256), blk>>>(c, cr, n4_bh);
    round_buf<<<(unsigned)((n4_hh + 255) / 256), blk>>>(w_ip_f, r_wipf, n4_hh);
    round_buf<<<(unsigned)((n4_hh + 255) / 256), blk>>>(w_ip_i, r_wipi, n4_hh);
    round_buf<<<(unsigned)((n4_hh + 255) / 256), blk>>>(w_ip_c, r_wipc, n4_hh);
    round_buf<<<(unsigned)((n4_hh + 255) / 256), blk>>>(w_ip_o, r_wipo, n4_hh);
    round_buf<<<(unsigned)((n4_hh + 255) / 256), blk>>>(w_forget, r_wf, n4_hh);
    round_buf<<<(unsigned)((n4_hh + 255) / 256), blk>>>(w_input,  r_wi, n4_hh);
    round_buf<<<(unsigned)((n4_hh + 255) / 256), blk>>>(w_c_dash, r_wc, n4_hh);
    round_buf<<<(unsigned)((n4_hh + 255) / 256), blk>>>(w_output, r_wo, n4_hh);
    round_buf<<<(unsigned)((n4_hh + 255) / 256), blk>>>(w_forget_c, r_pf, n4_hh);
    round_buf<<<(unsigned)((n4_hh + 255) / 256), blk>>>(w_input_c,  r_pi, n4_hh);
    round_buf<<<(unsigned)((n4_hh + 255) / 256), blk>>>(w_output_c, r_po, n4_hh);
    round_buf<<<(unsigned)((n4_wop + 255) / 256), blk>>>(w_op, wop, n4_wop);

    // ---- gate pre-activations: conversion-free, 2 CTAs/SM, single wave each ----
    sgemm<0, 3><<<g_h, blk>>>(xr, r_wipf, hr, r_wf, cr, r_pf, zf, 1024);
    sgemm<0, 3><<<g_h, blk>>>(xr, r_wipi, hr, r_wi, cr, r_pi, zi, 1024);
    sgemm<0, 2><<<g_h, blk>>>(xr, r_wipc, hr, r_wc, nullptr, nullptr, zc, 1024);
    sgemm<0, 2><<<g_h, blk>>>(xr, r_wipo, hr, r_wo, nullptr, nullptr, zo, 1024);

    lstm_ew1<<<(unsigned)(BH / 256), blk>>>(zf, zi, zc, c, ct_out, ctr, (int)BH);

    // zo += Ct @ w_output_c
    sgemm<1, 1><<<g_h, blk>>>(ctr, r_po, nullptr, nullptr, nullptr, nullptr, zo, 1024);

    lstm_ew2<<<(unsigned)(BH / 256), blk>>>(zo, ct_out, ht_out, htr, (int)BH);

    // Yt = sigmoid(Htr @ Wop) — R11-proven vocab config
    sgemm<2, 1><<<g_v, blk>>>(htr, wop, nullptr, nullptr, nullptr, nullptr, out, V_);
}

// round 17
// speedup vs baseline: 1.1622x; 1.1622x over previous
#include <cuda_runtime.h>
#include <mma.h>
#include <cstdint>

using namespace nvcuda;

#define B_ 4096
#define H_ 1024
#define V_ 32000

// -------- scratch (device globals: allocation-free per harness rules) --------
__device__ float g_zf[(size_t)B_ * H_];
__device__ float g_zi[(size_t)B_ * H_];
__device__ float g_zc[(size_t)B_ * H_];
__device__ float g_zo[(size_t)B_ * H_];
__device__ float g_ct[(size_t)B_ * H_];
__device__ float g_ht[(size_t)B_ * H_];
__device__ float g_htr[(size_t)B_ * H_];        // tf32-rounded Ht  (vocab A)
__device__ float g_ctr[(size_t)B_ * H_];        // tf32-rounded Ct  (peephole A)
__device__ float g_xr [(size_t)B_ * H_];        // tf32-rounded x
__device__ float g_hr [(size_t)B_ * H_];        // tf32-rounded h
__device__ float g_cr [(size_t)B_ * H_];        // tf32-rounded c
__device__ float g_w  [(size_t)11 * H_ * H_];   // 11 tf32-rounded [1024x1024] weights
__device__ float g_wop[(size_t)H_ * V_];        // tf32-rounded w_op

constexpr int BM = 128, BN = 128, BK = 32;
constexpr int APAD = 8, BPAD = 8;
constexpr int A_ROW = BK + APAD;          // 40 floats
constexpr int B_ROW = BN + BPAD;          // 136 floats
constexpr int A_STAGE = BM * A_ROW;       // 5120 floats
constexpr int B_STAGE = BK * B_ROW;       // 4352 floats
constexpr int SMEM_BYTES = 2 * (A_STAGE + B_STAGE) * 4;   // 75776

__device__ __forceinline__ float sigmoidf_(float x) {
    return 1.0f / (1.0f + expf(-x));
}

__device__ __forceinline__ void cp_async16(uint32_t dst, const void* src) {
    asm volatile("cp.async.cg.shared.global [%0], [%1], 16;\n" :: "r"(dst), "l"(src));
}
__device__ __forceinline__ void cp_commit() {
    asm volatile("cp.async.commit_group;\n" ::: "memory");
}
template <int N>
__device__ __forceinline__ void cp_wait() {
    asm volatile("cp.async.wait_group %0;\n" :: "n"(N) : "memory");
}

__device__ __forceinline__ float4 round4(float4 v) {
    v.x = wmma::__float_to_tf32(v.x);
    v.y = wmma::__float_to_tf32(v.y);
    v.z = wmma::__float_to_tf32(v.z);
    v.w = wmma::__float_to_tf32(v.w);
    return v;
}

// -------- batched tf32 pre-round: y selects buffer (3 BH-sized + 11 HH-sized) --------
// Each case names its parameter EXPLICITLY (no address-of-param indexing — that UB
// was the R16 correctness bug).
__global__ void round_all(
    const float* x, const float* h, const float* c,
    const float* w0, const float* w1, const float* w2, const float* w3,
    const float* w4, const float* w5, const float* w6, const float* w7,
    const float* w8, const float* w9, const float* w10)
{
    const size_t BH4 = (size_t)B_ * H_ / 4;   // 1,048,576 float4s
    const size_t HH  = (size_t)H_ * H_;
    const size_t HH4 = HH / 4;                //   262,144 float4s
    const int y = blockIdx.y;
    size_t i = (size_t)blockIdx.x * blockDim.x + threadIdx.x;

    const float* src; float* dst; size_t n4;
    switch (y) {
        case 0:  src = x;   dst = g_xr;            n4 = BH4; break;
        case 1:  src = h;   dst = g_hr;            n4 = BH4; break;
        case 2:  src = c;   dst = g_cr;            n4 = BH4; break;
        case 3:  src = w0;  dst = g_w + 0  * HH;   n4 = HH4; break;
        case 4:  src = w1;  dst = g_w + 1  * HH;   n4 = HH4; break;
        case 5:  src = w2;  dst = g_w + 2  * HH;   n4 = HH4; break;
        case 6:  src = w3;  dst = g_w + 3  * HH;   n4 = HH4; break;
        case 7:  src = w4;  dst = g_w + 4  * HH;   n4 = HH4; break;
        case 8:  src = w5;  dst = g_w + 5  * HH;   n4 = HH4; break;
        case 9:  src = w6;  dst = g_w + 6  * HH;   n4 = HH4; break;
        case 10: src = w7;  dst = g_w + 7  * HH;   n4 = HH4; break;
        case 11: src = w8;  dst = g_w + 8  * HH;   n4 = HH4; break;
        case 12: src = w9;  dst = g_w + 9  * HH;   n4 = HH4; break;
        default: src = w10; dst = g_w + 10 * HH;   n4 = HH4; break;
    }
    if (i < n4)
        ((float4*)dst)[i] = round4(((const float4*)src)[i]);
}

__global__ void round_wop(const float* __restrict__ src, float* __restrict__ dst)
{
    size_t i = ((size_t)blockIdx.x * 256 + threadIdx.x) * 4;
    *(float4*)(dst + i) = round4(*(const float4*)(src + i));
}
constexpr unsigned ROUND_WOP_BLOCKS = (unsigned)((size_t)H_ * V_ / (4 * 256));  // 32000
static_assert((size_t)ROUND_WOP_BLOCKS * 4 * 256 == (size_t)H_ * V_, "exact cover");

// ===== pipelined cp.async GEMM, conversion-free, 2 CTAs/SM (gates/peephole) =====
// Operands MUST be pre-rounded tf32. MODE: 0 = store, 1 = accumulate.
template <int MODE, int NPAIR>
__global__ __launch_bounds__(256, 2) void pgemm(
    const float* __restrict__ A0, const float* __restrict__ W0,
    const float* __restrict__ A1, const float* __restrict__ W1,
    const float* __restrict__ A2, const float* __restrict__ W2,
    float* __restrict__ C, int N)
{
    extern __shared__ __align__(16) float smem[];
    float* As = smem;                 // [2][BM][A_ROW]
    float* Bs = smem + 2 * A_STAGE;   // [2][BK][B_ROW]

    const int tid    = threadIdx.x;
    const int wid    = tid >> 5;
    const int warp_m = wid & 3;
    const int warp_n = wid >> 2;
    const int bm     = blockIdx.y * BM;
    const int bn     = blockIdx.x * BN;

    const uint32_t sbase = (uint32_t)__cvta_generic_to_shared(smem);

    wmma::fragment<wmma::accumulator, 16, 16, 8, float> acc[2][4];
    #pragma unroll
    for (int i = 0; i < 2; i++)
        #pragma unroll
        for (int j = 0; j < 4; j++) {
            if (MODE == 1) {
                const float* cp = C + (size_t)(bm + warp_m * 32 + i * 16) * N
                                    + (bn + warp_n * 64 + j * 16);
                wmma::load_matrix_sync(acc[i][j], cp, N, wmma::mem_row_major);
            } else {
                wmma::fill_fragment(acc[i][j], 0.0f);
            }
        }

    const float* Aps[3] = {A0, A1, A2};
    const float* Wps[3] = {W0, W1, W2};
    const int NS = NPAIR * 32;

    const int ar = tid >> 3;             // 0..31
    const int ac = (tid & 7) * 4;        // 0..28
    const int br = tid >> 5;             // 0..7
    const int bc = (tid & 31) * 4;       // 0..124

    auto load_stage = [&](int buf, int s) {
        const int p  = s >> 5;
        const int k0 = (s & 31) * BK;
        const float* __restrict__ A = Aps[p];
        const float* __restrict__ W = Wps[p];
        #pragma unroll
        for (int rr = 0; rr < 4; rr++) {
            uint32_t dst = sbase + (uint32_t)(buf * A_STAGE + (ar + rr * 32) * A_ROW + ac) * 4u;
            cp_async16(dst, A + (size_t)(bm + ar + rr * 32) * 1024 + k0 + ac);
        }
        #pragma unroll
        for (int rr = 0; rr < 4; rr++) {
            uint32_t dst = sbase + (uint32_t)(2 * A_STAGE + buf * B_STAGE + (br + rr * 8) * B_ROW + bc) * 4u;
            cp_async16(dst, W + (size_t)(k0 + br + rr * 8) * N + bn + bc);
        }
    };

    load_stage(0, 0);
    cp_commit();

    #pragma unroll 1
    for (int s = 0; s < NS; s++) {
        const int buf = s & 1;
        if (s + 1 < NS) {
            load_stage(buf ^ 1, s + 1);
            cp_commit();
            cp_wait<1>();
        } else {
            cp_wait<0>();
        }
        __syncthreads();

        const float* Ab    = As + buf * A_STAGE;
        const float* Bbase = Bs + buf * B_STAGE;

        #pragma unroll
        for (int kk = 0; kk < BK; kk += 8) {
            wmma::fragment<wmma::matrix_a, 16, 16, 8, wmma::precision::tf32, wmma::row_major> af[2];
            wmma::fragment<wmma::matrix_b, 16, 16, 8, wmma::precision::tf32, wmma::row_major> bf[4];
            #pragma unroll
            for (int i = 0; i < 2; i++)
                wmma::load_matrix_sync(af[i], Ab + (warp_m * 32 + i * 16) * A_ROW + kk, A_ROW);
            #pragma unroll
            for (int j = 0; j < 4; j++)
                wmma::load_matrix_sync(bf[j], Bbase + kk * B_ROW + warp_n * 64 + j * 16, B_ROW);
            #pragma unroll
            for (int i = 0; i < 2; i++)
                #pragma unroll
                for (int j = 0; j < 4; j++)
                    wmma::mma_sync(acc[i][j], af[i], bf[j], acc[i][j]);
        }
        __syncthreads();
    }

    #pragma unroll
    for (int i = 0; i < 2; i++)
        #pragma unroll
        for (int j = 0; j < 4; j++) {
            float* cp = C + (size_t)(bm + warp_m * 32 + i * 16) * N
                          + (bn + warp_n * 64 + j * 16);
            wmma::store_matrix_sync(cp, acc[i][j], N, wmma::mem_row_major);
        }
}

// ===== vocab GEMM: R11-proven config — conversion-free simple body, 2 CTAs/SM =====
__global__ __launch_bounds__(256, 2) void vocab_kernel(
    const float* __restrict__ A, const float* __restrict__ W,
    float* __restrict__ C, int N)
{
    __shared__ __align__(16) float As[BM][A_ROW];
    __shared__ __align__(16) float Bs[BK][B_ROW];

    const int tid    = threadIdx.x;
    const int wid    = tid >> 5;
    const int warp_m = wid & 3;
    const int warp_n = wid >> 2;
    const int bm     = blockIdx.y * BM;
    const int bn     = blockIdx.x * BN;

    wmma::fragment<wmma::accumulator, 16, 16, 8, float> acc[2][4];
    #pragma unroll
    for (int i = 0; i < 2; i++)
        #pragma unroll
        for (int j = 0; j < 4; j++)
            wmma::fill_fragment(acc[i][j], 0.0f);

    #pragma unroll 1
    for (int k0 = 0; k0 < 1024; k0 += BK) {
        {
            const int r = tid >> 3;
            const int cc = (tid & 7) * 4;
            #pragma unroll
            for (int rr = 0; rr < 4; rr++) {
                float4 v = *(const float4*)(A + (size_t)(bm + r + rr * 32) * 1024 + k0 + cc);
                *(float4*)&As[r + rr * 32][cc] = v;
            }
        }
        {
            const int r = tid >> 5;
            const int cc = (tid & 31) * 4;
            #pragma unroll
            for (int rr = 0; rr < 4; rr++) {
                float4 v = *(const float4*)(W + (size_t)(k0 + r + rr * 8) * N + bn + cc);
                *(float4*)&Bs[r + rr * 8][cc] = v;
            }
        }
        __syncthreads();

        #pragma unroll
        for (int kk = 0; kk < BK; kk += 8) {
            wmma::fragment<wmma::matrix_a, 16, 16, 8, wmma::precision::tf32, wmma::row_major> af[2];
            wmma::fragment<wmma::matrix_b, 16, 16, 8, wmma::precision::tf32, wmma::row_major> bf[4];
            #pragma unroll
            for (int i = 0; i < 2; i++)
                wmma::load_matrix_sync(af[i], &As[warp_m * 32 + i * 16][kk], A_ROW);
            #pragma unroll
            for (int j = 0; j < 4; j++)
                wmma::load_matrix_sync(bf[j], &Bs[kk][warp_n * 64 + j * 16], B_ROW);
            #pragma unroll
            for (int i = 0; i < 2; i++)
                #pragma unroll
                for (int j = 0; j < 4; j++)
                    wmma::mma_sync(acc[i][j], af[i], bf[j], acc[i][j]);
        }
        __syncthreads();
    }

    #pragma unroll
    for (int i = 0; i < 2; i++)
        #pragma unroll
        for (int j = 0; j < 4; j++) {
            #pragma unroll
            for (int t = 0; t < acc[i][j].num_elements; t++)
                acc[i][j].x[t] = sigmoidf_(acc[i][j].x[t]);
            float* cp = C + (size_t)(bm + warp_m * 32 + i * 16) * N
                          + (bn + warp_n * 64 + j * 16);
            wmma::store_matrix_sync(cp, acc[i][j], N, wmma::mem_row_major);
        }
}

// ======================= elementwise =======================
__global__ void lstm_ew1(const float* __restrict__ zf, const float* __restrict__ zi,
                         const float* __restrict__ zc, const float* __restrict__ c,
                         float* __restrict__ ct, float* __restrict__ ctr, int n)
{
    int i = blockIdx.x * blockDim.x + threadIdx.x;
    if (i < n) {
        float v = sigmoidf_(zf[i]) * c[i] + sigmoidf_(zi[i]) * tanhf(zc[i]);
        ct[i]  = v;
        ctr[i] = wmma::__float_to_tf32(v);
    }
}
__global__ void lstm_ew2(const float* __restrict__ zo, const float* __restrict__ ct,
                         float* __restrict__ ht, float* __restrict__ htr, int n)
{
    int i = blockIdx.x * blockDim.x + threadIdx.x;
    if (i < n) {
        float v = sigmoidf_(zo[i]) * tanhf(ct[i]);
        ht[i]  = v;
        htr[i] = wmma::__float_to_tf32(v);
    }
}

extern "C" void kernel_launch(void* const* d_in, const int* in_sizes, int n_in,
                              void* d_out, int out_size)
{
    const float* x          = (const float*)d_in[0];
    const float* h          = (const float*)d_in[1];
    const float* c          = (const float*)d_in[2];
    const float* w_forget   = (const float*)d_in[3];
    const float* w_input    = (const float*)d_in[4];
    const float* w_output   = (const float*)d_in[5];
    const float* w_c_dash   = (const float*)d_in[6];
    const float* w_forget_c = (const float*)d_in[7];
    const float* w_input_c  = (const float*)d_in[8];
    const float* w_output_c = (const float*)d_in[9];
    const float* w_op       = (const float*)d_in[10];
    const float* w_ip_f     = (const float*)d_in[11];
    const float* w_ip_i     = (const float*)d_in[12];
    const float* w_ip_o     = (const float*)d_in[13];
    const float* w_ip_c     = (const float*)d_in[14];
    float* out = (float*)d_out;

    cudaFuncSetAttribute((const void*)pgemm<0, 3>, cudaFuncAttributeMaxDynamicSharedMemorySize, SMEM_BYTES);
    cudaFuncSetAttribute((const void*)pgemm<0, 2>, cudaFuncAttributeMaxDynamicSharedMemorySize, SMEM_BYTES);
    cudaFuncSetAttribute((const void*)pgemm<1, 1>, cudaFuncAttributeMaxDynamicSharedMemorySize, SMEM_BYTES);

    float *zf, *zi, *zc, *zo, *ctbuf, *htbuf, *htr, *ctr, *xr, *hr, *cr, *wsc, *wop;
    cudaGetSymbolAddress((void**)&zf, g_zf);
    cudaGetSymbolAddress((void**)&zi, g_zi);
    cudaGetSymbolAddress((void**)&zc, g_zc);
    cudaGetSymbolAddress((void**)&zo, g_zo);
    cudaGetSymbolAddress((void**)&ctbuf, g_ct);
    cudaGetSymbolAddress((void**)&htbuf, g_ht);
    cudaGetSymbolAddress((void**)&htr, g_htr);
    cudaGetSymbolAddress((void**)&ctr, g_ctr);
    cudaGetSymbolAddress((void**)&xr, g_xr);
    cudaGetSymbolAddress((void**)&hr, g_hr);
    cudaGetSymbolAddress((void**)&cr, g_cr);
    cudaGetSymbolAddress((void**)&wsc, g_w);
    cudaGetSymbolAddress((void**)&wop, g_wop);

    const size_t BV = (size_t)B_ * V_;
    const size_t BH = (size_t)B_ * H_;
    const size_t HH = (size_t)H_ * H_;
    float* ht_out = ((size_t)out_size >= BV + 2 * BH) ? (out + BV)      : htbuf;
    float* ct_out = ((size_t)out_size >= BV + 2 * BH) ? (out + BV + BH) : ctbuf;

    dim3 blk(256);
    dim3 g_h(8, 32);        // gate/peephole grids
    dim3 g_v(250, 32);      // vocab grid

    float* r_wipf = wsc + 0  * HH;  float* r_wipi = wsc + 1  * HH;
    float* r_wipc = wsc + 2  * HH;  float* r_wipo = wsc + 3  * HH;
    float* r_wf   = wsc + 4  * HH;  float* r_wi   = wsc + 5  * HH;
    float* r_wc   = wsc + 6  * HH;  float* r_wo   = wsc + 7  * HH;
    float* r_pf   = wsc + 8  * HH;  float* r_pi   = wsc + 9  * HH;
    float* r_po   = wsc + 10 * HH;

    // ---- pre-round: one batched launch (14 buffers, grid.x covers BH4) + wop ----
    round_all<<<dim3((unsigned)(BH / 4 / 256), 14), blk>>>(
        x, h, c,
        w_ip_f, w_ip_i, w_ip_c, w_ip_o,      // -> slots 0..3
        w_forget, w_input, w_c_dash, w_output, // -> slots 4..7
        w_forget_c, w_input_c, w_output_c);    // -> slots 8..10
    round_wop<<<ROUND_WOP_BLOCKS, blk>>>(w_op, wop);

    // ---- gates: pipelined + 2 CTAs/SM, conversion-free ----
    pgemm<0, 3><<<g_h, blk, SMEM_BYTES>>>(xr, r_wipf, hr, r_wf, cr, r_pf, zf, 1024);
    pgemm<0, 3><<<g_h, blk, SMEM_BYTES>>>(xr, r_wipi, hr, r_wi, cr, r_pi, zi, 1024);
    pgemm<0, 2><<<g_h, blk, SMEM_BYTES>>>(xr, r_wipc, hr, r_wc, nullptr, nullptr, zc, 1024);
    pgemm<0, 2><<<g_h, blk, SMEM_BYTES>>>(xr, r_wipo, hr, r_wo, nullptr, nullptr, zo, 1024);

    lstm_ew1<<<(unsigned)(BH / 256), blk>>>(zf, zi, zc, c, ct_out, ctr, (int)BH);

    // zo += Ct @ w_output_c
    pgemm<1, 1><<<g_h, blk, SMEM_BYTES>>>(ctr, r_po, nullptr, nullptr, nullptr, nullptr, zo, 1024);

    lstm_ew2<<<(unsigned)(BH / 256), blk>>>(zo, ct_out, ht_out, htr, (int)BH);

    // Yt = sigmoid(Htr @ Wop)
    vocab_kernel<<<g_v, blk>>>(htr, wop, out, V_);
}